// round 17
// baseline (speedup 1.0000x reference)
#include <cuda_runtime.h>
#include <cstdint>

// ---------------- problem constants ----------------
#define NNODES 139425          // 65*65*33
#define NCELLS 131072          // 64*64*32
#define NACT   81920
#define EPSD   1.0e-7f
#define ATOL2  2.0e-12         // (1e-6)^2 * ||b||^2, ||b||^2 = 2
#define NCX 137280
#define NCY 137280
#define NCZ 135200
#define CG_ITERS 100
#define NBLK 137               // ceil(139425/1024)
#define NTHR 1024
#define DSMEM (2*4*1024*16)    // r, q tiles (float4): 131072 B

typedef unsigned long long u64t;
#define SGN2 0x8000000080000000ULL

// ---------------- device scratch ----------------
__device__ float4 g_r[NNODES*4];       // exchanged vector: residual r
__device__ float  g_sigma[NCELLS];
__device__ float  g_cx[NCX];
__device__ float  g_cy[NCY];
__device__ float  g_cz[NCZ];
__device__ double g_dotA[16];          // r.q accumulators
__device__ double g_dotB[16];          // r.r accumulators
__device__ float  g_xsel[32*16];
__device__ float  g_psel[32*16];       // slot-thread p accumulators
__device__ float  g_ab[32];            // alpha[0..15], beta[16..31]
__device__ float  g_gam[16];
__device__ int    g_froz[16];
__device__ unsigned g_cnt;
__device__ volatile unsigned g_rel2;

// ---------------- setup kernels ----------------
__global__ void k_init_sigma() {
    int t = blockIdx.x*blockDim.x + threadIdx.x;
    if (t < NCELLS) g_sigma[t] = 1.0e-8f;            // 1/AIR_RES
}

__global__ void k_scatter(const int* __restrict__ act, const float* __restrict__ model) {
    int t = blockIdx.x*blockDim.x + threadIdx.x;
    if (t < NACT) g_sigma[act[t]] = 1.0f / model[t];
}

__global__ void k_coeffs() {
    int t = blockIdx.x*blockDim.x + threadIdx.x;
    if (t < NCX) {
        int k = t % 33; int r = t / 33; int j = r % 65; int i = r / 65;
        float s = 0.f;
        for (int jj = j-1; jj <= j; ++jj)
            for (int kk = k-1; kk <= k; ++kk)
                if (jj >= 0 && jj < 64 && kk >= 0 && kk < 32)
                    s += g_sigma[(i*64 + jj)*32 + kk];
        g_cx[t] = 6.25f * s;                          // 0.25 * 25.0
    } else if (t < NCX + NCY) {
        int e = t - NCX;
        int k = e % 33; int r = e / 33; int j = r % 64; int i = r / 64;
        float s = 0.f;
        for (int ii = i-1; ii <= i; ++ii)
            for (int kk = k-1; kk <= k; ++kk)
                if (ii >= 0 && ii < 64 && kk >= 0 && kk < 32)
                    s += g_sigma[(ii*64 + j)*32 + kk];
        g_cy[e] = 6.25f * s;
    } else if (t < NCX + NCY + NCZ) {
        int e = t - NCX - NCY;
        int k = e % 32; int r = e / 32; int j = r % 65; int i = r / 65;
        float s = 0.f;
        for (int ii = i-1; ii <= i; ++ii)
            for (int jj = j-1; jj <= j; ++jj)
                if (ii >= 0 && ii < 64 && jj >= 0 && jj < 64)
                    s += g_sigma[(ii*64 + jj)*32 + k];
        g_cz[e] = 6.25f * s;
    }
}

// per-launch state reset (runs on every graph replay)
__global__ void k_zero() {
    int t = blockIdx.x*blockDim.x + threadIdx.x;
    if (t < NNODES*4) g_r[t] = make_float4(0.f,0.f,0.f,0.f);
    if (t < 32*16) { g_xsel[t] = 0.f; g_psel[t] = 0.f; }
    if (t < 32) g_ab[t] = 0.f;
    if (t < 16) {
        g_gam[t] = 2.f; g_froz[t] = 0;
        g_dotA[t] = 0.0; g_dotB[t] = 0.0;
    }
    // g_cnt / g_rel2 are monotone — never reset
}

// set r = b (separate kernel: ordering vs zero-fill via launch boundary)
__global__ void k_setb(const int* __restrict__ sa, const int* __restrict__ sb) {
    int s = threadIdx.x;
    if (s < 16) {
        float* rf = (float*)g_r;
        rf[sa[s]*16 + s]  = 1.0f;
        rf[sb[s]*16 + s] -= 1.0f;
    }
}

// ---------------- packed f32x2 helpers ----------------
__device__ __forceinline__ u64t pk2(float lo, float hi) {
    u64t r; asm("mov.b64 %0, {%1,%2};" : "=l"(r) : "f"(lo), "f"(hi)); return r;
}
__device__ __forceinline__ void upk2(u64t v, float& a, float& b) {
    asm("mov.b64 {%0,%1}, %2;" : "=f"(a), "=f"(b) : "l"(v));
}
__device__ __forceinline__ u64t fma2(u64t a, u64t b, u64t c) {
    u64t r; asm("fma.rn.f32x2 %0, %1, %2, %3;" : "=l"(r) : "l"(a), "l"(b), "l"(c)); return r;
}
__device__ __forceinline__ u64t mul2(u64t a, u64t b) {
    u64t r; asm("mul.rn.f32x2 %0, %1, %2;" : "=l"(r) : "l"(a), "l"(b)); return r;
}

// folded warp reduce of 4 values across 32 lanes: 9 SHFL instead of 20.
// After fold stages, lane 8k holds total for c=(lane>>3)&3.
#define QUADRED(v0, v1, v2, v3, u)                                             \
    {                                                                          \
        float t0 = __shfl_xor_sync(0xffffffffu, (v0), 16);                     \
        float t1 = __shfl_xor_sync(0xffffffffu, (v1), 16);                     \
        float t2 = __shfl_xor_sync(0xffffffffu, (v2), 16);                     \
        float t3 = __shfl_xor_sync(0xffffffffu, (v3), 16);                     \
        float b0 = (lane & 16) ? ((v2) + t2) : ((v0) + t0);                    \
        float b1 = (lane & 16) ? ((v3) + t3) : ((v1) + t1);                    \
        t0 = __shfl_xor_sync(0xffffffffu, b0, 8);                              \
        t1 = __shfl_xor_sync(0xffffffffu, b1, 8);                              \
        float cr = (lane & 8) ? (b1 + t1) : (b0 + t0);                         \
        cr += __shfl_xor_sync(0xffffffffu, cr, 4);                             \
        cr += __shfl_xor_sync(0xffffffffu, cr, 2);                             \
        cr += __shfl_xor_sync(0xffffffffu, cr, 1);                             \
        if ((lane & 7) == 0)                                                   \
            s_red[wid*16 + 4*(u) + ((lane >> 3) & 3)] = cr;                    \
    }

// cross-warp finish + atomic publish into 16 doubles
#define PUBRED(gdst)                                                           \
    {                                                                          \
        __syncthreads();                                                       \
        if (tid < 16) {                                                        \
            float acc = 0.f;                                                   \
            _Pragma("unroll")                                                  \
            for (int w = 0; w < 32; w++) acc += s_red[w*16 + tid];             \
            atomicAdd(&(gdst)[tid], (double)acc);                              \
        }                                                                      \
    }

// barrier arrive: counter-based; sets s_last in the last-arriving block
#define BAR_ARRIVE()                                                           \
    gen++;                                                                     \
    __syncthreads();                                                           \
    if (tid == 0) {                                                            \
        __threadfence();                                                       \
        unsigned old = atomicAdd(&g_cnt, 1u);                                  \
        s_last = (old == gen*(unsigned)NBLK - 1u) ? 1 : 0;                     \
    }                                                                          \
    __syncthreads();

#define BAR_WAIT()                                                             \
    if (tid == 0) {                                                            \
        while (g_rel2 < gen) { }                                               \
        __threadfence();                                                       \
    }                                                                          \
    __syncthreads();

// packed stencil accumulate: q += c*r + (-c)*rn  for both halves
#define ACC2(pn2)                                                              \
    {                                                                          \
        qa = fma2(c2, rp.x, qa); qa = fma2(n2, (pn2).x, qa);                   \
        qb = fma2(c2, rp.y, qb); qb = fma2(n2, (pn2).y, qb);                   \
    }

// ---------------- persistent CG kernel (2 barriers / iteration) ----------------
__global__ void __launch_bounds__(NTHR, 1)
k_persist(const int* __restrict__ rxm, const int* __restrict__ rxn)
{
    extern __shared__ float4 s_dyn[];
    float4* s_r = s_dyn;               // [4][1024] r (exchanged via g_r)
    float4* s_q = s_dyn + 4096;        // [4][1024] q (local only)
    ulonglong2* s_r2 = (ulonglong2*)s_r;
    ulonglong2* s_q2 = (ulonglong2*)s_q;

    const int tid = threadIdx.x;
    const int lane = tid & 31;
    const int wid  = tid >> 5;
    const int node = blockIdx.x*NTHR + tid;
    const bool valid = node < NNODES;

    int base4 = 0;
    float cxp=0.f, cxm=0.f, cyp=0.f, cym=0.f, czp=0.f, czm=0.f;
    if (valid) {
        int k = node % 33;
        int ij = node / 33;
        int j = ij % 65;
        int i = ij / 65;
        base4 = node * 4;
        if (i < 64) cxp = g_cx[(i*65 + j)*33 + k];
        if (i > 0)  cxm = g_cx[((i-1)*65 + j)*33 + k];
        if (j < 64) cyp = g_cy[(i*64 + j)*33 + k];
        if (j > 0)  cym = g_cy[(i*64 + (j-1))*33 + k];
        if (k < 32) czp = g_cz[(i*65 + j)*32 + k];
        if (k > 0)  czm = g_cz[(i*65 + j)*32 + (k-1)];
    }

    // receiver-slot ownership (32 distinct nodes)
    int slot = -1;
    if (valid) {
        for (int r2i = 0; r2i < 16; r2i++) {
            if (node == rxm[r2i]) slot = r2i;
            if (node == rxn[r2i]) slot = 16 + r2i;
        }
    }

    // init tiles: q = 0, r from g_r (holds b, set by k_setb)
    {
        float4 z = make_float4(0.f,0.f,0.f,0.f);
        #pragma unroll
        for (int u = 0; u < 4; u++) {
            s_q[u*1024+tid] = z;
            s_r[u*1024+tid] = valid ? g_r[base4+u] : z;
        }
    }

    __shared__ float  s_red[32*16];
    __shared__ __align__(16) float s_alpha[16];
    __shared__ __align__(16) float s_nalpha[16];
    __shared__ __align__(16) float s_beta[16];
    __shared__ int    s_last;
    if (tid < 16) s_beta[tid] = 0.f;
    __syncthreads();

    const u64t EPS2 = pk2(EPSD, EPSD);
    unsigned gen = g_rel2;       // stable generation base from previous launch

    #pragma unroll 1
    for (int it = 0; it < CG_ITERS; ++it) {
        // ---- slot-thread p recurrence: p = r + beta*p_old (32 threads) ----
        if (slot >= 0) {
            #pragma unroll
            for (int u = 0; u < 4; u++) {
                float4 rv = s_r[u*1024+tid];
                int o = slot*16 + 4*u;
                g_psel[o+0] = fmaf(s_beta[4*u+0], g_psel[o+0], rv.x);
                g_psel[o+1] = fmaf(s_beta[4*u+1], g_psel[o+1], rv.y);
                g_psel[o+2] = fmaf(s_beta[4*u+2], g_psel[o+2], rv.z);
                g_psel[o+3] = fmaf(s_beta[4*u+3], g_psel[o+3], rv.w);
            }
        }

        // ---- phase A: Ar stencil (packed); q = Ar + beta*q_old;
        //      partial r.q (alpha via exact A-conjugacy: p.q == r.q) ----
        #pragma unroll
        for (int u = 0; u < 4; u++) {
            ulonglong2 rp = s_r2[u*1024+tid];
            u64t qa = mul2(EPS2, rp.x);
            u64t qb = mul2(EPS2, rp.y);
            if (cxp != 0.f) {
                u64t c2 = pk2(cxp, cxp), n2 = c2 ^ SGN2;
                ulonglong2 pn2 = *(const ulonglong2*)&g_r[base4 + 8580 + u];
                ACC2(pn2);
            }
            if (cxm != 0.f) {
                u64t c2 = pk2(cxm, cxm), n2 = c2 ^ SGN2;
                ulonglong2 pn2 = *(const ulonglong2*)&g_r[base4 - 8580 + u];
                ACC2(pn2);
            }
            if (cyp != 0.f) {
                u64t c2 = pk2(cyp, cyp), n2 = c2 ^ SGN2;
                ulonglong2 pn2 = (tid + 33 < NTHR) ? s_r2[u*1024+tid+33]
                                 : *(const ulonglong2*)&g_r[base4 + 132 + u];
                ACC2(pn2);
            }
            if (cym != 0.f) {
                u64t c2 = pk2(cym, cym), n2 = c2 ^ SGN2;
                ulonglong2 pn2 = (tid >= 33) ? s_r2[u*1024+tid-33]
                                 : *(const ulonglong2*)&g_r[base4 - 132 + u];
                ACC2(pn2);
            }
            if (czp != 0.f) {
                u64t c2 = pk2(czp, czp), n2 = c2 ^ SGN2;
                ulonglong2 pn2 = (tid + 1 < NTHR) ? s_r2[u*1024+tid+1]
                                 : *(const ulonglong2*)&g_r[base4 + 4 + u];
                ACC2(pn2);
            }
            if (czm != 0.f) {
                u64t c2 = pk2(czm, czm), n2 = c2 ^ SGN2;
                ulonglong2 pn2 = (tid >= 1) ? s_r2[u*1024+tid-1]
                                 : *(const ulonglong2*)&g_r[base4 - 4 + u];
                ACC2(pn2);
            }
            // q = Ar + beta*q_old  (packed beta pairs)
            const u64t* bp = (const u64t*)s_beta;
            u64t b01 = bp[2*u], b23 = bp[2*u+1];
            ulonglong2 qo = s_q2[u*1024+tid];
            qa = fma2(b01, qo.x, qa);
            qb = fma2(b23, qo.y, qb);
            s_q2[u*1024+tid] = make_ulonglong2(qa, qb);
            // dot r.q
            u64t pr1 = mul2(rp.x, qa), pr2 = mul2(rp.y, qb);
            float f0, f1, f2, f3;
            upk2(pr1, f0, f1); upk2(pr2, f2, f3);
            QUADRED(f0, f1, f2, f3, u);
        }
        PUBRED(g_dotA);

        // ---- barrier B: last block computes alpha from g_dotA ----
        BAR_ARRIVE();
        if (s_last) {
            if (tid < 16) {
                double rq = g_dotA[tid];
                float a = g_froz[tid] ? 0.f : g_gam[tid] / (float)rq;
                g_ab[tid] = a;
                g_dotA[tid] = 0.0;
                __threadfence();
            }
            __syncthreads();
            if (tid == 0) { g_rel2 = gen; }
            __syncthreads();
        } else {
            BAR_WAIT();
        }
        if (tid < 16) {
            float a = g_ab[tid];
            s_alpha[tid] = a;
            s_nalpha[tid] = -a;
        }
        __syncthreads();

        // ---- phase B: r -= alpha q (packed, smem + publish);
        //      x_rx += alpha p (g_psel); r.r ----
        #pragma unroll
        for (int u = 0; u < 4; u++) {
            const u64t* nap = (const u64t*)s_nalpha;
            u64t na01 = nap[2*u], na23 = nap[2*u+1];
            ulonglong2 rp = s_r2[u*1024+tid];
            ulonglong2 qp = s_q2[u*1024+tid];
            u64t ra = fma2(na01, qp.x, rp.x);
            u64t rb = fma2(na23, qp.y, rp.y);
            ulonglong2 rn = make_ulonglong2(ra, rb);
            s_r2[u*1024+tid] = rn;
            if (valid) *(ulonglong2*)&g_r[base4+u] = rn;
            u64t rr1 = mul2(ra, ra), rr2 = mul2(rb, rb);
            float f0, f1, f2, f3;
            upk2(rr1, f0, f1); upk2(rr2, f2, f3);
            QUADRED(f0, f1, f2, f3, u);
        }
        if (slot >= 0) {
            #pragma unroll
            for (int u = 0; u < 4; u++) {
                int o = slot*16 + 4*u;
                g_xsel[o+0] += s_alpha[4*u+0] * g_psel[o+0];
                g_xsel[o+1] += s_alpha[4*u+1] * g_psel[o+1];
                g_xsel[o+2] += s_alpha[4*u+2] * g_psel[o+2];
                g_xsel[o+3] += s_alpha[4*u+3] * g_psel[o+3];
            }
        }
        if (it == CG_ITERS-1) break;   // final beta/barrier unused

        PUBRED(g_dotB);

        // ---- barrier C: last block computes beta/gamma/frozen ----
        BAR_ARRIVE();
        if (s_last) {
            if (tid < 16) {
                double gn = g_dotB[tid];
                float gnf = (float)gn;
                float b = g_froz[tid] ? 0.f : gnf / g_gam[tid];
                g_gam[tid] = gnf;
                if (gn <= ATOL2) g_froz[tid] = 1;
                g_ab[16 + tid] = b;
                g_dotB[tid] = 0.0;
                __threadfence();
            }
            __syncthreads();
            if (tid == 0) { g_rel2 = gen; }
            __syncthreads();
        } else {
            BAR_WAIT();
        }
        if (tid < 16) s_beta[tid] = g_ab[16 + tid];
        __syncthreads();
    }
}

// ---------------- loss ----------------
__global__ void k_loss(const float* __restrict__ infm, const float* __restrict__ start,
                       const float* __restrict__ ref, float* __restrict__ out) {
    __shared__ double sd[256];
    __shared__ double sm[256];
    int t = threadIdx.x;
    int s = t >> 4;                   // source index
    int r = t & 15;                   // receiver index
    float d = g_xsel[r*16 + s] - g_xsel[(16+r)*16 + s];
    float diff = d - ref[t];
    sd[t] = (double)diff * (double)diff;
    double lm = 0.0;
    for (int idx = t; idx < NACT; idx += 256) {
        float dd = infm[idx] - start[idx];
        lm += (double)dd * (double)dd;
    }
    sm[t] = lm;
    __syncthreads();
    for (int off = 128; off >= 1; off >>= 1) {
        if (t < off) { sd[t] += sd[t+off]; sm[t] += sm[t+off]; }
        __syncthreads();
    }
    if (t == 0) {
        float loss_data  = (float)(sd[0] / 256.0);
        float loss_model = (float)(sm[0] / (double)NACT);
        out[0] = loss_data;           // alpha = 0.0 -> total == loss_data
        out[1] = loss_data;
        out[2] = loss_model;
    }
}

// ---------------- launch ----------------
extern "C" void kernel_launch(void* const* d_in, const int* in_sizes, int n_in,
                              void* d_out, int out_size) {
    const float* infm  = (const float*)d_in[0];
    const float* start = (const float*)d_in[1];
    const float* dref  = (const float*)d_in[2];
    const int*   act   = (const int*)  d_in[3];
    const int*   sa    = (const int*)  d_in[4];
    const int*   sb    = (const int*)  d_in[5];
    const int*   rxm   = (const int*)  d_in[6];
    const int*   rxn   = (const int*)  d_in[7];
    float* out = (float*)d_out;

    static int attr_done = 0;
    if (!attr_done) {
        cudaFuncSetAttribute(k_persist, cudaFuncAttributeMaxDynamicSharedMemorySize, DSMEM);
        attr_done = 1;
    }

    k_init_sigma<<<(NCELLS+255)/256, 256>>>();
    k_scatter<<<(NACT+255)/256, 256>>>(act, infm);
    k_coeffs<<<(NCX+NCY+NCZ+255)/256, 256>>>();
    k_zero<<<(NNODES*4+255)/256, 256>>>();
    k_setb<<<1, 32>>>(sa, sb);
    k_persist<<<NBLK, NTHR, DSMEM>>>(rxm, rxn);
    k_loss<<<1, 256>>>(infm, start, dref, out);
}